// round 13
// baseline (speedup 1.0000x reference)
#include <cuda_runtime.h>
#include <cuda_fp16.h>
#include <math.h>
#include <stdint.h>

// ---------------- problem constants ----------------
#define BATCH    512
#define SEQT     25
#define CH       512
#define NWIN     5
#define POOLW    5
#define BS       2560          // BATCH * NWIN
#define NROWS    5120          // 2 * BS
#define NT       40            // 128-row tiles per dim
#define NBLK     820           // NT*(NT+1)/2 upper-triangular tiles
#define TM       128
#define TEMP_INV 10.0f
#define SHIFT    10.0f
#define NCHUNK   8             // 512 / 64

// ---------------- device scratch ----------------
__device__ __align__(16) __half g_znh[NROWS * CH];  // normalized rows, fp16
__device__ float g_rowS[NROWS];     // sum_j exp(logit-SHIFT), j != i
__device__ float g_rowPos[NROWS];   // positive logit per row
__device__ unsigned int g_done;     // last-CTA ticket (reset each replay by pool)

static __device__ __forceinline__ uint32_t smem_u32(const void* p) {
    uint32_t r;
    asm("{ .reg .u64 t; cvta.to.shared.u64 t, %1; cvt.u32.u64 %0, t; }" : "=r"(r) : "l"(p));
    return r;
}

#define LDSM_X4(R, addr) \
    asm volatile("ldmatrix.sync.aligned.m8n8.x4.shared.b16 {%0,%1,%2,%3}, [%4];" \
                 : "=r"((R)[0]), "=r"((R)[1]), "=r"((R)[2]), "=r"((R)[3]) : "r"(addr))

// fp16 in, fp32 accumulate (the FAST legacy form on sm_103a: R3/R6 evidence)
#define MMA16816F(C, A, B0, B1) \
    asm volatile("mma.sync.aligned.m16n8k16.row.col.f32.f16.f16.f32 " \
                 "{%0,%1,%2,%3}, {%4,%5,%6,%7}, {%8,%9}, {%0,%1,%2,%3};" \
                 : "+f"((C)[0]), "+f"((C)[1]), "+f"((C)[2]), "+f"((C)[3]) \
                 : "r"((A)[0]), "r"((A)[1]), "r"((A)[2]), "r"((A)[3]), \
                   "r"(B0), "r"(B1))

// ---------------------------------------------------------------------------
// Kernel A: adaptive-avg-pool + L2 normalize -> fp16 rows. 2 rows per block.
// Also zeros row accumulators, ticket, output (must run every replay).
// ---------------------------------------------------------------------------
__global__ __launch_bounds__(256) void pool_norm_kernel(const float* __restrict__ zi,
                                                        const float* __restrict__ zj,
                                                        float* __restrict__ out) {
    int half = threadIdx.x >> 7;
    int t    = threadIdx.x & 127;
    int r    = blockIdx.x * 2 + half;
    if (t == 0) {
        g_rowS[r] = 0.0f;
        if (r == 0) { out[0] = 0.0f; g_done = 0u; }
    }
    const float* src = (r < BS) ? zi : zj;
    int rr = (r < BS) ? r : r - BS;
    int b  = rr / NWIN;
    int w  = rr % NWIN;
    const float* base = src + ((size_t)(b * SEQT + w * POOLW)) * CH;

    int c0 = t * 4;
    float4 acc = make_float4(0.f, 0.f, 0.f, 0.f);
#pragma unroll
    for (int tt = 0; tt < POOLW; tt++) {
        float4 v = *(const float4*)(base + (size_t)tt * CH + c0);
        acc.x += v.x; acc.y += v.y; acc.z += v.z; acc.w += v.w;
    }
    acc.x *= 0.2f; acc.y *= 0.2f; acc.z *= 0.2f; acc.w *= 0.2f;

    float ss = acc.x * acc.x + acc.y * acc.y + acc.z * acc.z + acc.w * acc.w;
#pragma unroll
    for (int o = 16; o > 0; o >>= 1) ss += __shfl_xor_sync(0xffffffffu, ss, o);

    __shared__ float wsum[8];
    if ((threadIdx.x & 31) == 0) wsum[threadIdx.x >> 5] = ss;
    __syncthreads();
    float tot = wsum[half * 4] + wsum[half * 4 + 1] + wsum[half * 4 + 2] + wsum[half * 4 + 3];

    float inv = 1.0f / fmaxf(sqrtf(tot), 1e-8f);
    __half2 p0 = __floats2half2_rn(acc.x * inv, acc.y * inv);
    __half2 p1 = __floats2half2_rn(acc.z * inv, acc.w * inv);
    __half* dst = g_znh + (size_t)r * CH + c0;
    *(__half2*)(dst)     = p0;
    *(__half2*)(dst + 2) = p1;
}

// ---------------------------------------------------------------------------
// Kernel B: fp16-in/fp32-acc HMMA Gram tiles (upper triangle, 820 CTAs).
// 512 threads = 16 warps; warp (wr=wid&3, wc=wid>>2) computes rows wr*32..+32,
// cols wc*32..+32 (32x32 -> only 32 f32 acc regs/thread). K=64 chunks with
// register prefetch. smem 38KB -> 2 CTAs/SM -> 32 warps/SM.
// ---------------------------------------------------------------------------
__global__ __launch_bounds__(512, 2) void simclr_hmma_kernel(float* __restrict__ out) {
    // decode linear block id -> (rt, ct), ct >= rt
    int bid = blockIdx.x;
    int rt = (int)(0.5f * (81.0f - sqrtf(81.0f * 81.0f - 8.0f * (float)bid)));
    while ((rt + 1) * NT - ((rt + 1) * rt) / 2 <= bid) rt++;
    while (rt * NT - (rt * (rt - 1)) / 2 > bid) rt--;
    int ct = rt + bid - (rt * NT - (rt * (rt - 1)) / 2);

    const bool diag = (ct == rt);
    const bool haspos = (ct == rt + 20);      // +BS = 20 tiles

    __shared__ __align__(16) __half As[TM * 72];   // 18432 B (144B row stride)
    __shared__ __align__(16) __half Bsm[TM * 72];  // 18432 B
    __shared__ float rowsm[TM];
    __shared__ float colsm[TM];
    __shared__ int lastflag;

    int tid = threadIdx.x;
    int wid = tid >> 5, lid = tid & 31;
    int wr = wid & 3, wc = wid >> 2;        // wc in 0..3 (32-col slabs)
    int g = lid >> 2, t4 = lid & 3;

    if (tid < TM) { rowsm[tid] = 0.f; colsm[tid] = 0.f; }

    float acc[2][4][4];                      // [mi][na][quad] = 32 regs
#pragma unroll
    for (int mi = 0; mi < 2; mi++)
#pragma unroll
        for (int na = 0; na < 4; na++)
#pragma unroll
            for (int q = 0; q < 4; q++) acc[mi][na][q] = 0.f;

    const __half* Ag = g_znh + (size_t)rt * TM * CH;
    const __half* Bg = g_znh + (size_t)ct * TM * CH;
    uint32_t aBase = smem_u32(As), bBase = smem_u32(Bsm);

    // load slots: seg = tid + it*512 (it=0,1); row = seg>>3, c16 = seg&7
    int row0 = tid >> 3,         c16_0 = tid & 7;
    int row1 = (tid + 512) >> 3, c16_1 = (tid + 512) & 7;

    uint4 pa0, pa1, pb0, pb1;
    // prologue: chunk 0
    pa0 = *(const uint4*)(Ag + (size_t)row0 * CH + c16_0 * 8);
    pa1 = *(const uint4*)(Ag + (size_t)row1 * CH + c16_1 * 8);
    pb0 = *(const uint4*)(Bg + (size_t)row0 * CH + c16_0 * 8);
    pb1 = *(const uint4*)(Bg + (size_t)row1 * CH + c16_1 * 8);
    *(uint4*)((char*)As  + row0 * 144 + c16_0 * 16) = pa0;
    *(uint4*)((char*)As  + row1 * 144 + c16_1 * 16) = pa1;
    *(uint4*)((char*)Bsm + row0 * 144 + c16_0 * 16) = pb0;
    *(uint4*)((char*)Bsm + row1 * 144 + c16_1 * 16) = pb1;

    for (int c = 0; c < NCHUNK; c++) {
        __syncthreads();                       // smem chunk c ready

        if (c + 1 < NCHUNK) {
            int k0 = (c + 1) * 64;
            pa0 = *(const uint4*)(Ag + (size_t)row0 * CH + k0 + c16_0 * 8);
            pa1 = *(const uint4*)(Ag + (size_t)row1 * CH + k0 + c16_1 * 8);
            pb0 = *(const uint4*)(Bg + (size_t)row0 * CH + k0 + c16_0 * 8);
            pb1 = *(const uint4*)(Bg + (size_t)row1 * CH + k0 + c16_1 * 8);
        }

#pragma unroll
        for (int ks = 0; ks < 4; ks++) {
            int kk = ks * 16;
            uint32_t a[2][4];
#pragma unroll
            for (int mi = 0; mi < 2; mi++) {
                int r = wr * 32 + mi * 16 + (lid & 15);
                LDSM_X4(a[mi], aBase + r * 144 + (kk + (lid >> 4) * 8) * 2);
            }
            uint32_t bfr[2][4];
#pragma unroll
            for (int nb = 0; nb < 2; nb++) {
                int r = wc * 32 + nb * 16 + (lid & 15);
                LDSM_X4(bfr[nb], bBase + r * 144 + (kk + (lid >> 4) * 8) * 2);
            }
#pragma unroll
            for (int mi = 0; mi < 2; mi++)
#pragma unroll
                for (int na = 0; na < 4; na++)
                    MMA16816F(acc[mi][na], a[mi], bfr[na >> 1][na & 1], bfr[na >> 1][2 + (na & 1)]);
        }

        __syncthreads();                       // all warps done reading chunk c
        if (c + 1 < NCHUNK) {
            *(uint4*)((char*)As  + row0 * 144 + c16_0 * 16) = pa0;
            *(uint4*)((char*)As  + row1 * 144 + c16_1 * 16) = pa1;
            *(uint4*)((char*)Bsm + row0 * 144 + c16_0 * 16) = pb0;
            *(uint4*)((char*)Bsm + row1 * 144 + c16_1 * 16) = pb1;
        }
    }

    // ---- fused epilogue ----
    int gr0 = rt * TM, gc0 = ct * TM;
    float colacc[8];
#pragma unroll
    for (int q = 0; q < 8; q++) colacc[q] = 0.f;
    float rowpart[2][2] = {{0.f, 0.f}, {0.f, 0.f}};

#pragma unroll
    for (int mi = 0; mi < 2; mi++) {
#pragma unroll
        for (int na = 0; na < 4; na++) {
#pragma unroll
            for (int q = 0; q < 4; q++) {
                int h = q >> 1, e = q & 1;
                int rl = wr * 32 + mi * 16 + g + h * 8;
                int cl = wc * 32 + na * 8 + t4 * 2 + e;
                float sim = acc[mi][na][q];
                float ev = __expf(sim * TEMP_INV - SHIFT);
                if (diag && rl == cl) ev = 0.f;
                if (haspos && rl == cl) {
                    float lg = sim * TEMP_INV;
                    g_rowPos[gr0 + rl] = lg;
                    g_rowPos[gr0 + rl + BS] = lg;
                }
                rowpart[mi][h] += ev;
                colacc[na * 2 + e] += ev;
            }
        }
    }

    // row sums: reduce over t4 lanes (xor 1, 2); 4 wc-warps atomically combine
#pragma unroll
    for (int mi = 0; mi < 2; mi++)
#pragma unroll
        for (int h = 0; h < 2; h++) {
            float v = rowpart[mi][h];
            v += __shfl_xor_sync(0xffffffffu, v, 1);
            v += __shfl_xor_sync(0xffffffffu, v, 2);
            if (t4 == 0) atomicAdd(&rowsm[wr * 32 + mi * 16 + g + h * 8], v);
        }

    // col sums: reduce over g lanes (xor 4, 8, 16); 4 wr-warps combine
#pragma unroll
    for (int q = 0; q < 8; q++) {
        float v = colacc[q];
        v += __shfl_xor_sync(0xffffffffu, v, 4);
        v += __shfl_xor_sync(0xffffffffu, v, 8);
        v += __shfl_xor_sync(0xffffffffu, v, 16);
        if (g == 0) atomicAdd(&colsm[wc * 32 + (q >> 1) * 8 + t4 * 2 + (q & 1)], v);
    }
    __syncthreads();

    if (tid < TM) {
        atomicAdd(&g_rowS[gr0 + tid], rowsm[tid]);
        if (!diag) atomicAdd(&g_rowS[gc0 + tid], colsm[tid]);
    }

    // ---- last-CTA finalize ----
    __threadfence();
    __syncthreads();
    if (tid == 0) {
        unsigned int old = atomicAdd(&g_done, 1u);
        lastflag = (old == NBLK - 1) ? 1 : 0;
    }
    __syncthreads();
    if (lastflag) {
        __threadfence();
        float part = 0.f;
#pragma unroll
        for (int it = 0; it < NROWS / 512; it++) {
            int i = it * 512 + tid;
            part += SHIFT + __logf(g_rowS[i]) - g_rowPos[i];
        }
#pragma unroll
        for (int o = 16; o > 0; o >>= 1) part += __shfl_xor_sync(0xffffffffu, part, o);
        if (lid == 0) rowsm[wid] = part;
        __syncthreads();
        if (tid == 0) {
            float tot = 0.f;
#pragma unroll
            for (int w = 0; w < 16; w++) tot += rowsm[w];
            out[0] = tot / (float)NROWS;
        }
    }
}

// ---------------------------------------------------------------------------
extern "C" void kernel_launch(void* const* d_in, const int* in_sizes, int n_in,
                              void* d_out, int out_size) {
    const float* zi = (const float*)d_in[0];
    const float* zj = (const float*)d_in[1];
    float* out = (float*)d_out;

    pool_norm_kernel<<<NROWS / 2, 256>>>(zi, zj, out);
    simclr_hmma_kernel<<<NBLK, 512>>>(out);
}

// round 14
// speedup vs baseline: 1.5768x; 1.5768x over previous
#include <cuda_runtime.h>
#include <cuda_fp16.h>
#include <math.h>
#include <stdint.h>

// ---------------- problem constants ----------------
#define BATCH    512
#define SEQT     25
#define CH       512
#define NWIN     5
#define POOLW    5
#define BS       2560          // BATCH * NWIN
#define NROWS    5120          // 2 * BS
#define NT       40            // 128-row tiles per dim
#define NBLK     820           // NT*(NT+1)/2 upper-triangular tiles
#define TM       128
#define TEMP_INV 10.0f
#define SHIFT    10.0f
#define NCHUNK   8             // 512 / 64
#define BUFSTRIDE 36864        // one buffer: A(128*144) + B(128*144)
#define DSMEM    (2 * BUFSTRIDE)   // 73728 B dynamic

// ---------------- device scratch ----------------
__device__ __align__(16) __half g_znh[NROWS * CH];  // normalized rows, fp16
__device__ float g_rowS[NROWS];     // sum_j exp(logit-SHIFT), j != i
__device__ float g_rowPos[NROWS];   // positive logit per row
__device__ unsigned int g_done;     // last-CTA ticket (reset each replay by pool)

static __device__ __forceinline__ uint32_t smem_u32(const void* p) {
    uint32_t r;
    asm("{ .reg .u64 t; cvta.to.shared.u64 t, %1; cvt.u32.u64 %0, t; }" : "=r"(r) : "l"(p));
    return r;
}

#define LDSM_X4(R, addr) \
    asm volatile("ldmatrix.sync.aligned.m8n8.x4.shared.b16 {%0,%1,%2,%3}, [%4];" \
                 : "=r"((R)[0]), "=r"((R)[1]), "=r"((R)[2]), "=r"((R)[3]) : "r"(addr))

// fp16 in, fp16 accumulate (32 acc regs -> leaves room for 32 prefetch regs)
#define MMA16816H(C, A, B0, B1) \
    asm volatile("mma.sync.aligned.m16n8k16.row.col.f16.f16.f16.f16 " \
                 "{%0,%1}, {%2,%3,%4,%5}, {%6,%7}, {%0,%1};" \
                 : "+r"((C)[0]), "+r"((C)[1]) \
                 : "r"((A)[0]), "r"((A)[1]), "r"((A)[2]), "r"((A)[3]), \
                   "r"(B0), "r"(B1))

// ---------------------------------------------------------------------------
// Kernel A: adaptive-avg-pool + L2 normalize -> fp16 rows. 2 rows per block.
// Also zeros row accumulators, ticket, output (must run every replay).
// ---------------------------------------------------------------------------
__global__ __launch_bounds__(256) void pool_norm_kernel(const float* __restrict__ zi,
                                                        const float* __restrict__ zj,
                                                        float* __restrict__ out) {
    int half = threadIdx.x >> 7;
    int t    = threadIdx.x & 127;
    int r    = blockIdx.x * 2 + half;
    if (t == 0) {
        g_rowS[r] = 0.0f;
        if (r == 0) { out[0] = 0.0f; g_done = 0u; }
    }
    const float* src = (r < BS) ? zi : zj;
    int rr = (r < BS) ? r : r - BS;
    int b  = rr / NWIN;
    int w  = rr % NWIN;
    const float* base = src + ((size_t)(b * SEQT + w * POOLW)) * CH;

    int c0 = t * 4;
    float4 acc = make_float4(0.f, 0.f, 0.f, 0.f);
#pragma unroll
    for (int tt = 0; tt < POOLW; tt++) {
        float4 v = *(const float4*)(base + (size_t)tt * CH + c0);
        acc.x += v.x; acc.y += v.y; acc.z += v.z; acc.w += v.w;
    }
    acc.x *= 0.2f; acc.y *= 0.2f; acc.z *= 0.2f; acc.w *= 0.2f;

    float ss = acc.x * acc.x + acc.y * acc.y + acc.z * acc.z + acc.w * acc.w;
#pragma unroll
    for (int o = 16; o > 0; o >>= 1) ss += __shfl_xor_sync(0xffffffffu, ss, o);

    __shared__ float wsum[8];
    if ((threadIdx.x & 31) == 0) wsum[threadIdx.x >> 5] = ss;
    __syncthreads();
    float tot = wsum[half * 4] + wsum[half * 4 + 1] + wsum[half * 4 + 2] + wsum[half * 4 + 3];

    float inv = 1.0f / fmaxf(sqrtf(tot), 1e-8f);
    __half2 p0 = __floats2half2_rn(acc.x * inv, acc.y * inv);
    __half2 p1 = __floats2half2_rn(acc.z * inv, acc.w * inv);
    __half* dst = g_znh + (size_t)r * CH + c0;
    *(__half2*)(dst)     = p0;
    *(__half2*)(dst + 2) = p1;
}

// ---------------------------------------------------------------------------
// Kernel B: fp16 HMMA Gram tiles (upper triangle, 820 CTAs), DOUBLE-BUFFERED
// K=64 chunks in 73.7KB dynamic smem -> ONE barrier per chunk, STS overlapped
// with MMA. 256 threads, warp (wr,wc): rows wr*32..+32, cols wc*64..+64.
// Register prefetch (32 regs) feeds the next buffer. Fused epilogue +
// last-CTA finalize. Carveout=100 => 2 CTAs/SM.
// ---------------------------------------------------------------------------
__global__ __launch_bounds__(256, 2) void simclr_hmma_kernel(float* __restrict__ out) {
    // decode linear block id -> (rt, ct), ct >= rt
    int bid = blockIdx.x;
    int rt = (int)(0.5f * (81.0f - sqrtf(81.0f * 81.0f - 8.0f * (float)bid)));
    while ((rt + 1) * NT - ((rt + 1) * rt) / 2 <= bid) rt++;
    while (rt * NT - (rt * (rt - 1)) / 2 > bid) rt--;
    int ct = rt + bid - (rt * NT - (rt * (rt - 1)) / 2);

    const bool diag = (ct == rt);
    const bool haspos = (ct == rt + 20);      // +BS = 20 tiles

    extern __shared__ __align__(16) char tiles[];   // [2][A 18432 | B 18432]
    __shared__ float rowsm[TM];
    __shared__ float colsm[TM];
    __shared__ int lastflag;

    int tid = threadIdx.x;
    int wid = tid >> 5, lid = tid & 31;
    int wr = wid & 3, wc = wid >> 2;
    int g = lid >> 2, t4 = lid & 3;

    if (tid < TM) { rowsm[tid] = 0.f; colsm[tid] = 0.f; }

    uint32_t acc[2][8][2];
#pragma unroll
    for (int mi = 0; mi < 2; mi++)
#pragma unroll
        for (int na = 0; na < 8; na++) { acc[mi][na][0] = 0u; acc[mi][na][1] = 0u; }

    const __half* Ag = g_znh + (size_t)rt * TM * CH;
    const __half* Bg = g_znh + (size_t)ct * TM * CH;
    uint32_t sbase = smem_u32(tiles);

    // per-thread load slots: idx = tid + it*256 -> row = idx>>3, ch = idx&7
    int lrow[4], lch[4];
#pragma unroll
    for (int it = 0; it < 4; it++) {
        int idx = tid + it * 256;
        lrow[it] = idx >> 3;
        lch[it]  = idx & 7;
    }

    uint4 pa[4], pb[4];
    // prologue: fetch chunk 0 into regs, store into buffer 0
#pragma unroll
    for (int it = 0; it < 4; it++) {
        pa[it] = *(const uint4*)(Ag + (size_t)lrow[it] * CH + lch[it] * 8);
        pb[it] = *(const uint4*)(Bg + (size_t)lrow[it] * CH + lch[it] * 8);
    }
#pragma unroll
    for (int it = 0; it < 4; it++) {
        *(uint4*)(tiles + lrow[it] * 144 + lch[it] * 16) = pa[it];
        *(uint4*)(tiles + 18432 + lrow[it] * 144 + lch[it] * 16) = pb[it];
    }

    for (int c = 0; c < NCHUNK; c++) {
        __syncthreads();      // chunk c visible; chunk c-1 readers all done

        // prefetch chunk c+1 into registers (overlaps the MMAs below)
        if (c + 1 < NCHUNK) {
            int k0 = (c + 1) * 64;
#pragma unroll
            for (int it = 0; it < 4; it++) {
                pa[it] = *(const uint4*)(Ag + (size_t)lrow[it] * CH + k0 + lch[it] * 8);
                pb[it] = *(const uint4*)(Bg + (size_t)lrow[it] * CH + k0 + lch[it] * 8);
            }
        }

        uint32_t aB = sbase + (uint32_t)(c & 1) * BUFSTRIDE;
        uint32_t bB = aB + 18432;
#pragma unroll
        for (int ks = 0; ks < 4; ks++) {
            int kk = ks * 16;
            uint32_t a[2][4];
#pragma unroll
            for (int mi = 0; mi < 2; mi++) {
                int r = wr * 32 + mi * 16 + (lid & 15);
                LDSM_X4(a[mi], aB + r * 144 + (kk + (lid >> 4) * 8) * 2);
            }
            uint32_t bfr[4][4];
#pragma unroll
            for (int nb = 0; nb < 4; nb++) {
                int r = wc * 64 + nb * 16 + (lid & 15);
                LDSM_X4(bfr[nb], bB + r * 144 + (kk + (lid >> 4) * 8) * 2);
            }
#pragma unroll
            for (int mi = 0; mi < 2; mi++)
#pragma unroll
                for (int na = 0; na < 8; na++)
                    MMA16816H(acc[mi][na], a[mi], bfr[na >> 1][na & 1], bfr[na >> 1][2 + (na & 1)]);
        }

        // store chunk c+1 into the OTHER buffer — its previous readers finished
        // before the barrier at the top of this iteration, so no extra sync.
        if (c + 1 < NCHUNK) {
            char* nxt = tiles + ((c + 1) & 1) * BUFSTRIDE;
#pragma unroll
            for (int it = 0; it < 4; it++) {
                *(uint4*)(nxt + lrow[it] * 144 + lch[it] * 16) = pa[it];
                *(uint4*)(nxt + 18432 + lrow[it] * 144 + lch[it] * 16) = pb[it];
            }
        }
    }

    // ---- fused epilogue ----
    int gr0 = rt * TM, gc0 = ct * TM;
    float colacc[16];
#pragma unroll
    for (int q = 0; q < 16; q++) colacc[q] = 0.f;
    float rowpart[2][2] = {{0.f, 0.f}, {0.f, 0.f}};

#pragma unroll
    for (int mi = 0; mi < 2; mi++) {
#pragma unroll
        for (int na = 0; na < 8; na++) {
#pragma unroll
            for (int h = 0; h < 2; h++) {
                float2 pr = __half22float2(*(const __half2*)&acc[mi][na][h]);
#pragma unroll
                for (int e = 0; e < 2; e++) {
                    int rl = wr * 32 + mi * 16 + g + h * 8;
                    int cl = wc * 64 + na * 8 + t4 * 2 + e;
                    float sim = (e == 0) ? pr.x : pr.y;
                    float ev = __expf(sim * TEMP_INV - SHIFT);
                    if (diag && rl == cl) ev = 0.f;
                    if (haspos && rl == cl) {
                        float lg = sim * TEMP_INV;
                        g_rowPos[gr0 + rl] = lg;
                        g_rowPos[gr0 + rl + BS] = lg;
                    }
                    rowpart[mi][h] += ev;
                    colacc[na * 2 + e] += ev;
                }
            }
        }
    }

    // row sums: reduce over t4 lanes (xor 1, 2)
#pragma unroll
    for (int mi = 0; mi < 2; mi++)
#pragma unroll
        for (int h = 0; h < 2; h++) {
            float v = rowpart[mi][h];
            v += __shfl_xor_sync(0xffffffffu, v, 1);
            v += __shfl_xor_sync(0xffffffffu, v, 2);
            if (t4 == 0) atomicAdd(&rowsm[wr * 32 + mi * 16 + g + h * 8], v);
        }

    // col sums: reduce over g lanes (xor 4, 8, 16)
#pragma unroll
    for (int q = 0; q < 16; q++) {
        float v = colacc[q];
        v += __shfl_xor_sync(0xffffffffu, v, 4);
        v += __shfl_xor_sync(0xffffffffu, v, 8);
        v += __shfl_xor_sync(0xffffffffu, v, 16);
        if (g == 0) atomicAdd(&colsm[wc * 64 + (q >> 1) * 8 + t4 * 2 + (q & 1)], v);
    }
    __syncthreads();

    if (tid < TM) {
        atomicAdd(&g_rowS[gr0 + tid], rowsm[tid]);
        if (!diag) atomicAdd(&g_rowS[gc0 + tid], colsm[tid]);
    }

    // ---- last-CTA finalize ----
    __threadfence();
    __syncthreads();
    if (tid == 0) {
        unsigned int old = atomicAdd(&g_done, 1u);
        lastflag = (old == NBLK - 1) ? 1 : 0;
    }
    __syncthreads();
    if (lastflag) {
        __threadfence();
        float part = 0.f;
#pragma unroll
        for (int it = 0; it < NROWS / 256; it++) {
            int i = it * 256 + tid;
            part += SHIFT + __logf(g_rowS[i]) - g_rowPos[i];
        }
#pragma unroll
        for (int o = 16; o > 0; o >>= 1) part += __shfl_xor_sync(0xffffffffu, part, o);
        if (lid == 0) rowsm[wid] = part;
        __syncthreads();
        if (tid == 0) {
            float tot = 0.f;
#pragma unroll
            for (int w = 0; w < 8; w++) tot += rowsm[w];
            out[0] = tot / (float)NROWS;
        }
    }
}

// ---------------------------------------------------------------------------
extern "C" void kernel_launch(void* const* d_in, const int* in_sizes, int n_in,
                              void* d_out, int out_size) {
    const float* zi = (const float*)d_in[0];
    const float* zj = (const float*)d_in[1];
    float* out = (float*)d_out;

    // Large dynamic smem + max carveout so TWO 73.7KB CTAs fit per SM.
    cudaFuncSetAttribute(simclr_hmma_kernel,
                         cudaFuncAttributeMaxDynamicSharedMemorySize, DSMEM);
    cudaFuncSetAttribute(simclr_hmma_kernel,
                         cudaFuncAttributePreferredSharedMemoryCarveout, 100);

    pool_norm_kernel<<<NROWS / 2, 256>>>(zi, zj, out);
    simclr_hmma_kernel<<<NBLK, 256, DSMEM>>>(out);
}